// round 3
// baseline (speedup 1.0000x reference)
#include <cuda_runtime.h>

#define B_DIM 128
#define N_DIM 131072

constexpr int THREADS        = 256;
constexpr int NBLOCKS        = 512;   // <= 148 SMs * 4 co-resident blocks => single wave
constexpr int BLOCKS_PER_ROW = 16;
constexpr int ROWS_PER_GRP   = NBLOCKS / BLOCKS_PER_ROW;     // 32
constexpr int NGROUPS        = B_DIM / ROWS_PER_GRP;         // 4 (even -> sense replay-safe)
constexpr int ELEMS_PER_BLK  = N_DIM / BLOCKS_PER_ROW;       // 8192
constexpr int VEC_PER_BLK    = ELEMS_PER_BLK / 4;            // 2048 float4
constexpr int VEC_PER_THR    = VEC_PER_BLK / THREADS;        // 8
constexpr int SMEM_BYTES     = ELEMS_PER_BLK * 4;            // 32 KB

// Persistent scratch (zero-initialized at module load; barrier self-resets so
// graph replays are deterministic).
__device__ float        g_partial[B_DIM * BLOCKS_PER_ROW];
__device__ unsigned int g_bar_count;
__device__ unsigned int g_bar_sense;

__device__ __forceinline__ void grid_barrier(unsigned int& sense)
{
    __syncthreads();
    const unsigned int s = sense ^ 1u;
    if (threadIdx.x == 0) {
        __threadfence();
        unsigned int arrived = atomicAdd(&g_bar_count, 1u);
        if (arrived == NBLOCKS - 1) {
            atomicExch(&g_bar_count, 0u);   // self-reset (replay-safe)
            __threadfence();
            atomicExch(&g_bar_sense, s);
        } else {
            while (*((volatile unsigned int*)&g_bar_sense) != s)
                __nanosleep(40);
        }
    }
    sense = s;
    __syncthreads();
    __threadfence();
}

__device__ __forceinline__ float transition_likelihood(
    float x, float nz, float cterm, float ob, float pwv, float& w_out)
{
    float mean = fmaf(x, 0.5f, 25.0f * __fdividef(x, fmaf(x, x, 1.0f))) + cterm;
    float np   = fmaf(nz, 3.16227766f, mean);          // * sqrt(10)
    float om   = np * np * 0.05f;                      // np^2 / 20
    float d    = ob - om;
    float lp   = fmaf(-0.5f * d, d, -0.9189385332f);   // -0.5*log(2*pi)
    w_out      = pwv * __expf(lp);
    return np;
}

__global__ void __launch_bounds__(THREADS, 4)
pf_persistent_kernel(const float* __restrict__ particles,
                     const float* __restrict__ pw,
                     const float* __restrict__ obs,
                     const float* __restrict__ noise,
                     const int*   __restrict__ tstep,
                     float* __restrict__ out_np,
                     float* __restrict__ out_w)
{
    extern __shared__ float4 w_s[];        // [VEC_PER_BLK] = 32 KB

    const int bi   = blockIdx.x;
    const int seg  = bi & (BLOCKS_PER_ROW - 1);
    const int rgrp = bi >> 4;              // row within group (0..31)

    const float t     = (float)__ldg(tstep);
    const float cterm = 8.0f * cosf(1.2f * t);

    unsigned int sense = 0;

    for (int g = 0; g < NGROUPS; g++) {
        const int  r    = g * ROWS_PER_GRP + rgrp;
        const long base = (long)r * N_DIM + (long)seg * ELEMS_PER_BLK;
        const float ob  = __ldg(obs + r);

        const float4* p4  = (const float4*)(particles + base);
        const float4* n4  = (const float4*)(noise + base);
        const float4* w4  = (const float4*)(pw + base);
        float4* onp4      = (float4*)(out_np + base);
        float4* ow4       = (float4*)(out_w + base);

        // ---- Phase 1: transition + likelihood; w -> smem; partial sum ----
        float lsum = 0.0f;
        #pragma unroll
        for (int i = 0; i < VEC_PER_THR; i++) {
            const int off = i * THREADS + threadIdx.x;
            float4 x  = p4[off];
            float4 nz = n4[off];
            float4 pv = w4[off];
            float4 np_, wv;
            np_.x = transition_likelihood(x.x, nz.x, cterm, ob, pv.x, wv.x);
            np_.y = transition_likelihood(x.y, nz.y, cterm, ob, pv.y, wv.y);
            np_.z = transition_likelihood(x.z, nz.z, cterm, ob, pv.z, wv.z);
            np_.w = transition_likelihood(x.w, nz.w, cterm, ob, pv.w, wv.w);
            onp4[off] = np_;
            w_s[off]  = wv;
            lsum += (wv.x + wv.y) + (wv.z + wv.w);
        }

        // Block-reduce lsum -> one partial per block (no atomics, no zeroing)
        __shared__ float red[THREADS / 32];
        #pragma unroll
        for (int s = 16; s > 0; s >>= 1)
            lsum += __shfl_xor_sync(0xFFFFFFFFu, lsum, s);
        const int lane = threadIdx.x & 31;
        const int wid  = threadIdx.x >> 5;
        if (lane == 0) red[wid] = lsum;
        __syncthreads();
        if (wid == 0) {
            float v = (lane < THREADS / 32) ? red[lane] : 0.0f;
            #pragma unroll
            for (int s = 4; s > 0; s >>= 1)
                v += __shfl_xor_sync(0xFFFFFFFFu, v, s);
            if (lane == 0)
                g_partial[r * BLOCKS_PER_ROW + seg] = v;
        }

        grid_barrier(sense);

        // ---- Phase 2: gather row sum, normalize smem-resident w ----
        float rsum = 0.0f;
        #pragma unroll
        for (int j = 0; j < BLOCKS_PER_ROW; j++)
            rsum += __ldcg(&g_partial[r * BLOCKS_PER_ROW + j]);
        const float inv = __frcp_rn(rsum);

        #pragma unroll
        for (int i = 0; i < VEC_PER_THR; i++) {
            const int off = i * THREADS + threadIdx.x;
            float4 wv = w_s[off];
            wv.x *= inv; wv.y *= inv; wv.z *= inv; wv.w *= inv;
            ow4[off] = wv;
        }
        // Next group's barrier orders g_partial reuse; smem is block-private.
    }
}

extern "C" void kernel_launch(void* const* d_in, const int* in_sizes, int n_in,
                              void* d_out, int out_size)
{
    const float* particles = (const float*)d_in[0];   // [B, N, 1]
    const float* pw        = (const float*)d_in[1];   // [B, N]
    const float* obs       = (const float*)d_in[2];   // [B, 1]
    const float* noise     = (const float*)d_in[3];   // [B, N, 1]
    // d_in[4] = uniforms — dead in the reference (resample output unused)
    const int*   tstep     = (const int*)d_in[5];     // scalar

    float* out_np = (float*)d_out;                    // [B, N, 1]
    float* out_w  = out_np + (size_t)B_DIM * N_DIM;   // [B, N]

    pf_persistent_kernel<<<NBLOCKS, THREADS, SMEM_BYTES>>>(
        particles, pw, obs, noise, tstep, out_np, out_w);
}

// round 4
// speedup vs baseline: 1.2514x; 1.2514x over previous
#include <cuda_runtime.h>

#define B_DIM 128
#define N_DIM 131072

constexpr int THREADS    = 256;
constexpr int PER_THREAD = 8;                           // float4s per thread
constexpr int CHUNK      = THREADS * 4 * PER_THREAD;    // 8192 elements per block
constexpr int BLOCKS_X   = N_DIM / CHUNK;               // 16 blocks per row

// L2-staged scratch for unnormalized weights (64 MB; device global — legal
// scratch, zero-allocation). In steady state across graph replays these lines
// live in L2 (126 MB) and are rewritten before eviction matters.
__device__ float g_scratch_w[(size_t)B_DIM * N_DIM];
// One partial sum per block — written every launch, no zeroing needed.
__device__ float g_partial[B_DIM * BLOCKS_X];

__device__ __forceinline__ float transition_likelihood(
    float x, float nz, float cterm, float ob, float pwv, float& w_out)
{
    // UNGM transition: x/2 + 25*x/(x^2+1) + 8*cos(1.2*t) + noise*sqrt(10)
    float mean = fmaf(x, 0.5f, 25.0f * __fdividef(x, fmaf(x, x, 1.0f))) + cterm;
    float np   = fmaf(nz, 3.16227766f, mean);
    float om   = np * np * 0.05f;                       // np^2 / 20
    float d    = ob - om;
    float lp   = fmaf(-0.5f * d, d, -0.9189385332f);    // -0.5*log(2*pi)
    w_out      = pwv * __expf(lp);
    return np;
}

__global__ void __launch_bounds__(THREADS)
pf_step_kernel(const float* __restrict__ particles,
               const float* __restrict__ pw,
               const float* __restrict__ obs,
               const float* __restrict__ noise,
               const int*   __restrict__ tstep,
               float* __restrict__ out_np)
{
    const int  b    = blockIdx.y;
    const long base = (long)b * N_DIM + (long)blockIdx.x * CHUNK;

    const float t     = (float)__ldg(tstep);
    const float cterm = 8.0f * cosf(1.2f * t);
    const float ob    = __ldg(obs + b);

    const float4* p4  = (const float4*)(particles + base);
    const float4* n4  = (const float4*)(noise + base);
    const float4* w4  = (const float4*)(pw + base);
    float4* onp4      = (float4*)(out_np + base);
    float4* sw4       = (float4*)(g_scratch_w + base);

    float lsum = 0.0f;

    #pragma unroll
    for (int i = 0; i < PER_THREAD; i++) {
        const int off = i * THREADS + threadIdx.x;
        // Streaming reads: evict-first, keep L2 for the scratch.
        float4 x  = __ldcs(p4 + off);
        float4 nz = __ldcs(n4 + off);
        float4 pv = __ldcs(w4 + off);
        float4 np_, wv;
        np_.x = transition_likelihood(x.x, nz.x, cterm, ob, pv.x, wv.x);
        np_.y = transition_likelihood(x.y, nz.y, cterm, ob, pv.y, wv.y);
        np_.z = transition_likelihood(x.z, nz.z, cterm, ob, pv.z, wv.z);
        np_.w = transition_likelihood(x.w, nz.w, cterm, ob, pv.w, wv.w);
        __stcs(onp4 + off, np_);        // streaming store (pure output)
        sw4[off] = wv;                  // write-back store -> stays in L2
        lsum += (wv.x + wv.y) + (wv.z + wv.w);
    }

    // Block reduction -> one partial per block (no atomics, no zero pass)
    __shared__ float red[THREADS / 32];
    #pragma unroll
    for (int s = 16; s > 0; s >>= 1)
        lsum += __shfl_xor_sync(0xFFFFFFFFu, lsum, s);
    const int lane = threadIdx.x & 31;
    const int wid  = threadIdx.x >> 5;
    if (lane == 0) red[wid] = lsum;
    __syncthreads();
    if (wid == 0) {
        float v = (lane < THREADS / 32) ? red[lane] : 0.0f;
        #pragma unroll
        for (int s = 4; s > 0; s >>= 1)
            v += __shfl_xor_sync(0xFFFFFFFFu, v, s);
        if (lane == 0)
            g_partial[b * BLOCKS_X + blockIdx.x] = v;
    }
}

__global__ void __launch_bounds__(THREADS)
normalize_kernel(float* __restrict__ out_w)
{
    const int b = blockIdx.y;

    // Row sum from the 16 per-block partials (L1/L2-resident after 1st warp).
    float rsum = 0.0f;
    #pragma unroll
    for (int j = 0; j < BLOCKS_X; j++)
        rsum += __ldg(&g_partial[b * BLOCKS_X + j]);
    const float inv = __frcp_rn(rsum);

    const long base = (long)b * N_DIM + (long)blockIdx.x * CHUNK;
    const float4* sw4 = (const float4*)(g_scratch_w + base);
    float4* ow4       = (float4*)(out_w + base);

    #pragma unroll
    for (int i = 0; i < PER_THREAD; i++) {
        const int off = i * THREADS + threadIdx.x;
        float4 v = __ldcs(sw4 + off);   // L2 hit; evict after use
        v.x *= inv; v.y *= inv; v.z *= inv; v.w *= inv;
        __stcs(ow4 + off, v);           // streaming store (pure output)
    }
}

extern "C" void kernel_launch(void* const* d_in, const int* in_sizes, int n_in,
                              void* d_out, int out_size)
{
    const float* particles = (const float*)d_in[0];   // [B, N, 1]
    const float* pw        = (const float*)d_in[1];   // [B, N]
    const float* obs       = (const float*)d_in[2];   // [B, 1]
    const float* noise     = (const float*)d_in[3];   // [B, N, 1]
    // d_in[4] = uniforms — dead in the reference (resample output unused)
    const int*   tstep     = (const int*)d_in[5];     // scalar

    float* out_np = (float*)d_out;                    // [B, N, 1]
    float* out_w  = out_np + (size_t)B_DIM * N_DIM;   // [B, N]

    dim3 grid(BLOCKS_X, B_DIM);

    pf_step_kernel<<<grid, THREADS>>>(particles, pw, obs, noise, tstep, out_np);
    normalize_kernel<<<grid, THREADS>>>(out_w);
}